// round 14
// baseline (speedup 1.0000x reference)
#include <cuda_runtime.h>
#include <cuda_fp16.h>
#include <cstdint>

#define NN 100000
#define EE 1000000
#define FEAT 128
#define NLAB 2048
#define MPAD 100096            // 391 * 256
#define KE1 128                // single-term fp16: A=xhi, B=Whi
#define NBLK_SCAN 98

// GEMM tiling
#define TM 256
#define A_CH_BYTES (TM * 128)          // 32768 (one 64-K chunk of A)
#define B_CH_BYTES (128 * 128)         // 16384 (one 64-K chunk of B)
#define B_TILE_BYTES (2 * B_CH_BYTES)  // 32768 (full 128-K B tile)
#define B_OFF (2 * A_CH_BYTES)         // 65536
#define SMEM_F (B_OFF + 2 * B_TILE_BYTES)  // 131072

typedef unsigned long long ull;

// ======================= device scratch =====================================
static __device__ __align__(16) __half g_Asplit[(size_t)MPAD * KE1];   // 25.6 MB
static __device__ __align__(16) __half g_Bsplit1[FEAT * KE1];          // 32 KB
static __device__ __align__(16) __half g_Bsplit2[FEAT * KE1];          // 32 KB
static __device__ __align__(16) __half g_BsplitO[NLAB * KE1];          // 512 KB
static __device__ __align__(16) __half g_Hh[(size_t)MPAD * FEAT];      // 25.6 MB
static __device__ ull   g_packed[NN];      // count<<42 | sum(ew)*2^32
static __device__ float g_dinv[NN];
static __device__ int   g_cnt[NN];
static __device__ int   g_colptr[NN];
static __device__ int   g_cursor[NN];
static __device__ int   g_bsum[128];
static __device__ int   g_bofs[128];
static __device__ __align__(8) uint2 g_edge[EE];   // (src, w) packed, 8 MB

// ======================= helpers ============================================
__device__ __forceinline__ uint32_t smem_u32(const void* p) {
    uint32_t a;
    asm("{ .reg .u64 t; cvta.to.shared.u64 t, %1; cvt.u32.u64 %0, t; }" : "=r"(a) : "l"(p));
    return a;
}
#define SWZ128(x) ((x) ^ (((x) >> 3) & 0x70))

__device__ __forceinline__ void cpa16(uint32_t s, const void* g) {
    asm volatile("cp.async.cg.shared.global [%0], [%1], 16;"
                 :: "r"(s), "l"(__cvta_generic_to_global(g)) : "memory");
}
__device__ __forceinline__ void cpa_commit() {
    asm volatile("cp.async.commit_group;" ::: "memory");
}
__device__ __forceinline__ void cpa_wait1() {
    asm volatile("cp.async.wait_group 1;" ::: "memory");
}
__device__ __forceinline__ void ldmA4(uint32_t* r, uint32_t addr) {
    asm volatile("ldmatrix.sync.aligned.m8n8.x4.shared.b16 {%0,%1,%2,%3}, [%4];"
                 : "=r"(r[0]), "=r"(r[1]), "=r"(r[2]), "=r"(r[3]) : "r"(addr));
}
__device__ __forceinline__ void mma16816(float* d, const uint32_t* a, uint32_t b0, uint32_t b1) {
    asm volatile(
        "mma.sync.aligned.m16n8k16.row.col.f32.f16.f16.f32 "
        "{%0,%1,%2,%3}, {%4,%5,%6,%7}, {%8,%9}, {%0,%1,%2,%3};"
        : "+f"(d[0]), "+f"(d[1]), "+f"(d[2]), "+f"(d[3])
        : "r"(a[0]), "r"(a[1]), "r"(a[2]), "r"(a[3]), "r"(b0), "r"(b1));
}

// ======================= graph preprocessing ================================
__global__ void k_init() {
    int i = blockIdx.x * blockDim.x + threadIdx.x;
    if (i < NN) g_packed[i] = 0ULL;
}
__global__ void k_hist(const int* __restrict__ col, const float* __restrict__ ew) {
    int e = blockIdx.x * blockDim.x + threadIdx.x;
    if (e < EE) {
        ull p = (1ULL << 42) | (ull)(ew[e] * 4294967296.0f);
        atomicAdd(&g_packed[col[e]], p);
    }
}
__global__ void k_scanA() {
    __shared__ int s[1024];
    int t = threadIdx.x;
    int i = blockIdx.x * 1024 + t;
    int v = (i < NN) ? (int)(g_packed[i] >> 42) : 0;
    s[t] = v;
    __syncthreads();
    for (int off = 1; off < 1024; off <<= 1) {
        int add = (t >= off) ? s[t - off] : 0;
        __syncthreads();
        s[t] += add;
        __syncthreads();
    }
    if (i < NN) g_colptr[i] = s[t] - v;
    if (t == 1023) g_bsum[blockIdx.x] = s[1023];
}
__global__ void k_scanB() {   // 1 block, 128 threads
    __shared__ int s[128];
    int t = threadIdx.x;
    int v = (t < NBLK_SCAN) ? g_bsum[t] : 0;
    s[t] = v;
    __syncthreads();
    for (int off = 1; off < 128; off <<= 1) {
        int add = (t >= off) ? s[t - off] : 0;
        __syncthreads();
        s[t] += add;
        __syncthreads();
    }
    if (t < NBLK_SCAN) g_bofs[t] = s[t] - v;
}
__global__ void k_scanC() {
    int i = blockIdx.x * 1024 + threadIdx.x;
    if (i < NN) {
        ull p = g_packed[i];
        int cnt = (int)(p >> 42);
        float wsum = (float)((double)(p & ((1ULL << 42) - 1)) * (1.0 / 4294967296.0));
        int ex = g_colptr[i] + g_bofs[blockIdx.x];
        g_colptr[i] = ex;
        g_cursor[i] = ex;
        g_cnt[i] = cnt;
        g_dinv[i] = rsqrtf(1.0f + wsum);
    }
}
// one atomic + ONE packed 8B scattered store per edge
__global__ void k_fill(const int* __restrict__ row, const int* __restrict__ col,
                       const float* __restrict__ ew) {
    int e = blockIdx.x * blockDim.x + threadIdx.x;
    if (e < EE) {
        int c = col[e], r = row[e];
        int pos = atomicAdd(&g_cursor[c], 1);
        float w = g_dinv[r] * ew[e] * g_dinv[c];
        uint2 pk = {(uint32_t)r, __float_as_uint(w)};
        g_edge[pos] = pk;
    }
}

// ======================= splits (single-term) ================================
__global__ void k_splitA1(const float* __restrict__ emb, const int* __restrict__ idx) {
    const size_t total = (size_t)NN * FEAT;
    for (size_t i = (size_t)blockIdx.x * blockDim.x + threadIdx.x; i < total;
         i += (size_t)gridDim.x * blockDim.x) {
        int m = (int)(i >> 7), k = (int)(i & 127);
        float v = emb[(size_t)idx[m] * FEAT + k];
        g_Asplit[(size_t)m * KE1 + k] = __float2half(v);
    }
}
__global__ void k_splitBall(const float* __restrict__ W1, const float* __restrict__ W2,
                            const float* __restrict__ Wout) {
    int i = blockIdx.x * blockDim.x + threadIdx.x;
    if (i < FEAT * FEAT) {
        int nr = i >> 7, k = i & 127;
        g_Bsplit1[nr * 128 + k] = __float2half(W1[k * FEAT + nr]);
    } else if (i < 2 * FEAT * FEAT) {
        int j = i - FEAT * FEAT;
        int nr = j >> 7, k = j & 127;
        g_Bsplit2[nr * 128 + k] = __float2half(W2[k * FEAT + nr]);
    } else {
        int j = i - 2 * FEAT * FEAT;
        if (j < NLAB * FEAT) {
            int nr = j >> 7, k = j & 127;
            g_BsplitO[nr * 128 + k] = __float2half(Wout[(size_t)k * NLAB + nr]);
        }
    }
}

// compile-time B-buffer selection (runtime pointer param caused spill — R11)
template <int BSEL>
__device__ __forceinline__ const __half* bsel_ptr() {
    if (BSEL == 0) return g_Bsplit1;
    if (BSEL == 1) return g_Bsplit2;
    return g_BsplitO;
}

// ======================= mma.sync GEMM (R13-proven body, frozen) ============
template <int LDA, int LDB, bool HALF_OUT, int BSEL>
__global__ void __launch_bounds__(512, 1)
gemm_kernel(float* __restrict__ Cext, int ldC, int nIters, int Mreal,
            const float* __restrict__ bias) {
    extern __shared__ char smem[];
    uint32_t sb = smem_u32(smem);
    int tid = threadIdx.x, lid = tid & 31, wid = tid >> 5;
    int warp_m = wid >> 2, warp_n = wid & 3;
    int m0 = blockIdx.x * TM;
    int n0_base = blockIdx.y * nIters;      // units of 128-col tiles

    const __half* Ag = g_Asplit + (size_t)m0 * LDA;

    // prologue group 0: full A tile (2 chunk slabs) + B tile of first n-iter
    #pragma unroll
    for (int c = 0; c < 2; c++) {
        for (int i = tid; i < TM * 8; i += 512) {
            int r = i >> 3, s = i & 7;
            cpa16(sb + c * A_CH_BYTES + SWZ128(r * 128 + s * 16),
                  Ag + (size_t)r * LDA + c * 64 + s * 8);
        }
    }
    {
        const __half* Bg = bsel_ptr<BSEL>() + (size_t)(n0_base * 128) * LDB;
        for (int i = tid; i < 128 * 16; i += 512) {
            int r = i >> 4, s = i & 15;
            uint32_t off = (uint32_t)((s >> 3) * B_CH_BYTES) +
                           SWZ128(r * 128 + (s & 7) * 16);
            cpa16(sb + B_OFF + off, Bg + (size_t)r * LDB + s * 8);
        }
    }
    cpa_commit();

    const int a_row = warp_m * 64 + (lid & 7) + ((lid >> 3) & 1) * 8;
    const int a_ks  = (lid >> 4) * 8;
    const int b_row = warp_n * 32 + (lid & 7) + ((lid >> 4) & 1) * 8;
    const int b_ks  = ((lid >> 3) & 1) * 8;

    for (int it = 0; it < nIters; it++) {
        int buf = it & 1;
        if (it + 1 < nIters) {
            const __half* Bg = bsel_ptr<BSEL>() +
                               (size_t)((n0_base + it + 1) * 128) * LDB;
            uint32_t bb = sb + B_OFF + (buf ^ 1) * B_TILE_BYTES;
            for (int i = tid; i < 128 * 16; i += 512) {
                int r = i >> 4, s = i & 15;
                uint32_t off = (uint32_t)((s >> 3) * B_CH_BYTES) +
                               SWZ128(r * 128 + (s & 7) * 16);
                cpa16(bb + off, Bg + (size_t)r * LDB + s * 8);
            }
        }
        cpa_commit();
        cpa_wait1();
        __syncthreads();

        float acc[4][4][4];
        #pragma unroll
        for (int mi = 0; mi < 4; mi++)
            #pragma unroll
            for (int nj = 0; nj < 4; nj++)
                #pragma unroll
                for (int q = 0; q < 4; q++) acc[mi][nj][q] = 0.0f;

        for (int h = 0; h < 2; h++) {
            uint32_t Ab = sb + h * A_CH_BYTES;
            uint32_t Bb = sb + B_OFF + buf * B_TILE_BYTES + h * B_CH_BYTES;
            #pragma unroll
            for (int ks = 0; ks < 4; ks++) {
                uint32_t a[4][4], b[2][4];
                #pragma unroll
                for (int mi = 0; mi < 4; mi++)
                    ldmA4(a[mi], Ab + SWZ128((a_row + mi * 16) * 128 + (a_ks + ks * 16) * 2));
                #pragma unroll
                for (int bi = 0; bi < 2; bi++)
                    ldmA4(b[bi], Bb + SWZ128((b_row + bi * 16) * 128 + (b_ks + ks * 16) * 2));
                #pragma unroll
                for (int mi = 0; mi < 4; mi++)
                    #pragma unroll
                    for (int nj = 0; nj < 4; nj++)
                        mma16816(acc[mi][nj], a[mi], b[nj >> 1][(nj & 1) * 2],
                                 b[nj >> 1][(nj & 1) * 2 + 1]);
            }
        }

        int n0 = (n0_base + it) * 128;
        #pragma unroll
        for (int mi = 0; mi < 4; mi++) {
            int r0 = m0 + warp_m * 64 + mi * 16 + (lid >> 2);
            #pragma unroll
            for (int nj = 0; nj < 4; nj++) {
                int col = n0 + warp_n * 32 + nj * 8 + ((lid & 3) << 1);
                if (HALF_OUT) {
                    if (r0 < Mreal) {
                        __half2 h2 = __floats2half2_rn(acc[mi][nj][0], acc[mi][nj][1]);
                        *(__half2*)(g_Hh + (size_t)r0 * FEAT + col) = h2;
                    }
                    if (r0 + 8 < Mreal) {
                        __half2 h2 = __floats2half2_rn(acc[mi][nj][2], acc[mi][nj][3]);
                        *(__half2*)(g_Hh + (size_t)(r0 + 8) * FEAT + col) = h2;
                    }
                } else {
                    float bx = bias[col];
                    float by = bias[col + 1];
                    if (r0 < Mreal) {
                        float2 o = {acc[mi][nj][0] + bx, acc[mi][nj][1] + by};
                        *(float2*)(Cext + (size_t)r0 * ldC + col) = o;
                    }
                    if (r0 + 8 < Mreal) {
                        float2 o = {acc[mi][nj][2] + bx, acc[mi][nj][3] + by};
                        *(float2*)(Cext + (size_t)(r0 + 8) * ldC + col) = o;
                    }
                }
            }
        }
        __syncthreads();
    }
}

// ======================= SpMM over fp16 H (packed edges, 8-deep MLP) ========
__device__ __forceinline__ void h4_fma(float4& acc, uint2 v, float w) {
    __half2 lo = *(__half2*)&v.x, hi = *(__half2*)&v.y;
    float2 f0 = __half22float2(lo), f1 = __half22float2(hi);
    acc.x += w * f0.x; acc.y += w * f0.y;
    acc.z += w * f1.x; acc.w += w * f1.y;
}
__global__ void k_spmm(const float* __restrict__ bias) {
    int gw = (blockIdx.x * blockDim.x + threadIdx.x) >> 5;
    int lane = threadIdx.x & 31;
    if (gw >= NN) return;
    const uint2* H2 = (const uint2*)g_Hh;    // 32 x uint2 per row (128 halves)
    float di = g_dinv[gw];
    float s = di * di;
    float4 acc = {0.f, 0.f, 0.f, 0.f};
    h4_fma(acc, H2[(size_t)gw * 32 + lane], s);
    int start = g_colptr[gw];
    int len = g_cnt[gw];
    int j = 0;
    for (; j + 8 <= len; j += 8) {
        uint2 e[8], v[8];
        #pragma unroll
        for (int q = 0; q < 8; q++) e[q] = g_edge[start + j + q];
        #pragma unroll
        for (int q = 0; q < 8; q++) v[q] = H2[(size_t)e[q].x * 32 + lane];
        #pragma unroll
        for (int q = 0; q < 8; q++) h4_fma(acc, v[q], __uint_as_float(e[q].y));
    }
    for (; j < len; j++) {
        uint2 e = g_edge[start + j];
        h4_fma(acc, H2[(size_t)e.x * 32 + lane], __uint_as_float(e.y));
    }
    float4 b4 = ((const float4*)bias)[lane];
    acc.x = fmaxf(acc.x + b4.x, 0.0f);
    acc.y = fmaxf(acc.y + b4.y, 0.0f);
    acc.z = fmaxf(acc.z + b4.z, 0.0f);
    acc.w = fmaxf(acc.w + b4.w, 0.0f);

    __half2 hp0 = __floats2half2_rn(acc.x, acc.y);
    __half2 hp1 = __floats2half2_rn(acc.z, acc.w);
    uint2 hv = {*(uint32_t*)&hp0, *(uint32_t*)&hp1};
    *(uint2*)(g_Asplit + (size_t)gw * KE1 + lane * 4) = hv;
}

// ======================= launch =============================================
extern "C" void kernel_launch(void* const* d_in, const int* in_sizes, int n_in,
                              void* d_out, int out_size) {
    const int*   node_idx = (const int*)d_in[0];
    const int*   ei       = (const int*)d_in[1];
    const float* ew       = (const float*)d_in[2];
    const float* emb      = (const float*)d_in[3];
    const float* W1       = (const float*)d_in[4];
    const float* b1       = (const float*)d_in[5];
    const float* W2       = (const float*)d_in[6];
    const float* b2       = (const float*)d_in[7];
    const float* Wout     = (const float*)d_in[8];
    const float* bout     = (const float*)d_in[9];
    float* out = (float*)d_out;
    const int* row = ei;
    const int* col = ei + EE;

    cudaFuncSetAttribute((const void*)gemm_kernel<KE1, KE1, true, 0>,
                         cudaFuncAttributeMaxDynamicSharedMemorySize, SMEM_F);
    cudaFuncSetAttribute((const void*)gemm_kernel<KE1, KE1, true, 1>,
                         cudaFuncAttributeMaxDynamicSharedMemorySize, SMEM_F);
    cudaFuncSetAttribute((const void*)gemm_kernel<KE1, KE1, false, 2>,
                         cudaFuncAttributeMaxDynamicSharedMemorySize, SMEM_F);

    const int gemm_grid = MPAD / TM;                 // 391
    const int spmm_grid = (NN + 7) / 8;
    const int splitB_grid = (2 * FEAT * FEAT + NLAB * FEAT + 255) / 256;

    // #1-2: input conversions (independent of graph preprocessing)
    k_splitA1<<<4096, 256>>>(emb, node_idx);
    k_splitBall<<<splitB_grid, 256>>>(W1, W2, Wout);
    // #3: preprocessing init
    k_init<<<(NN + 255) / 256, 256>>>();
    // #4: layer-1 GEMM (profiling slot)
    gemm_kernel<KE1, KE1, true, 0><<<gemm_grid, 512, SMEM_F>>>(
        nullptr, FEAT, 1, MPAD, nullptr);
    // #5-9: CSC build + symmetric norm
    k_hist<<<(EE + 255) / 256, 256>>>(col, ew);
    k_scanA<<<NBLK_SCAN, 1024>>>();
    k_scanB<<<1, 128>>>();
    k_scanC<<<NBLK_SCAN, 1024>>>();
    k_fill<<<(EE + 255) / 256, 256>>>(row, col, ew);
    // #10: layer-1 aggregate
    k_spmm<<<spmm_grid, 256>>>(b1);
    // #11-12: layer 2
    gemm_kernel<KE1, KE1, true, 1><<<gemm_grid, 512, SMEM_F>>>(
        nullptr, FEAT, 1, MPAD, nullptr);
    k_spmm<<<spmm_grid, 256>>>(b2);
    // #13: output layer, grid (391, 4), 4 n-iters each
    gemm_kernel<KE1, KE1, false, 2><<<dim3(gemm_grid, 4), 512, SMEM_F>>>(
        out, NLAB, 4, NN, bout);
}